// round 5
// baseline (speedup 1.0000x reference)
#include <cuda_runtime.h>
#include <math.h>

#define LQ 1024
#define NQ 128
#define BQ 32
#define CQ 32
#define TQ (LQ / CQ)          // 32 steps per chunk

#define P1B (CQ * 10)         // 320 blocks x 16 warp-tasks = 160 tasks/chunk
#define P2B BQ                // 32 blocks (one per batch)
#define P3B ((CQ * BQ) / 16)  // 64 blocks x 16 warps = 1024 (chunk,batch) pairs
#define NBLK (P1B + P2B + P3B)

// Scratch (device globals; no allocation)
__device__ float g_M[CQ][NQ][NQ];   // chunk transition [c][j][i] (column-major) 2 MB
__device__ float g_P[CQ][BQ][NQ];   // particular end states
__device__ float g_S[CQ][BQ][NQ];   // chunk start states
__device__ int   g_p1done;          // completed phase1 blocks
__device__ int   g_p2cnt[CQ];       // batches whose g_S[c] is published

__global__ void hippo_reset() {
    if (threadIdx.x == 0) g_p1done = 0;
    if (threadIdx.x < CQ) g_p2cnt[threadIdx.x] = 0;
}

// ---------------------------------------------------------------------------
// One bilinear HiPPO-LegS step with ANALYTIC coefficients (no table).
//   D = 2t+i+1, r = sqrt(2i+1):
//   a=(2t-i)/D  b=2t*r/D  e=a-1/D  f=-2r/D
//   sigma_i = a sigma_{i-1} + b s_i ;  s'_i = e s_i + f sigma_{i-1} + u_i
// Lane l owns states 4l..4l+3: local compose -> 32-lane Kogge-Stone scan of
// (A,W) -> exclusive sigma -> reconstruction. Coef math is independent of the
// state chain so it hides under the shfl latency.
// ---------------------------------------------------------------------------
__device__ __forceinline__ void hippo_step(
    float& s0, float& s1, float& s2, float& s3,
    float tt, float i0f, float r0, float r1, float r2, float r3,
    float u0, float u1, float u2, float u3, int lane)
{
    float d0   = tt + i0f + 1.0f;
    float inv0 = __fdividef(1.0f, d0);
    float inv1 = __fdividef(1.0f, d0 + 1.0f);
    float inv2 = __fdividef(1.0f, d0 + 2.0f);
    float inv3 = __fdividef(1.0f, d0 + 3.0f);
    float gg = tt - i0f;
    float a0 = gg * inv0, a1 = (gg - 1.0f) * inv1,
          a2 = (gg - 2.0f) * inv2, a3 = (gg - 3.0f) * inv3;
    float b0 = tt * r0 * inv0, b1 = tt * r1 * inv1,
          b2 = tt * r2 * inv2, b3 = tt * r3 * inv3;
    float e0 = a0 - inv0, e1 = a1 - inv1, e2 = a2 - inv2, e3 = a3 - inv3;
    float f0 = -2.0f * r0 * inv0, f1 = -2.0f * r1 * inv1,
          f2 = -2.0f * r2 * inv2, f3 = -2.0f * r3 * inv3;

    float W = b0 * s0;
    float A = a0;
    W = fmaf(a1, W, b1 * s1); A *= a1;
    W = fmaf(a2, W, b2 * s2); A *= a2;
    W = fmaf(a3, W, b3 * s3); A *= a3;
    #pragma unroll
    for (int d = 1; d < 32; d <<= 1) {
        float Ao = __shfl_up_sync(0xffffffffu, A, d);
        float Wo = __shfl_up_sync(0xffffffffu, W, d);
        if (lane >= d) { W = fmaf(A, Wo, W); A *= Ao; }
    }
    float sig = __shfl_up_sync(0xffffffffu, W, 1);
    if (lane == 0) sig = 0.f;

    float t0 = fmaf(e0, s0, fmaf(f0, sig, u0)); sig = fmaf(a0, sig, b0 * s0);
    float t1 = fmaf(e1, s1, fmaf(f1, sig, u1)); sig = fmaf(a1, sig, b1 * s1);
    float t2 = fmaf(e2, s2, fmaf(f2, sig, u2)); sig = fmaf(a2, sig, b2 * s2);
    float t3 = fmaf(e3, s3, fmaf(f3, sig, u3));
    s0 = t0; s1 = t1; s2 = t2; s3 = t3;
}

// ---------------------------------------------------------------------------
// Fused kernel. Block ranges (consumers at HIGHER indices than producers so
// in-order wave dispatch can never deadlock):
//   [0, P1B)            phase1: build M_c columns + particular end states
//   [P1B, P1B+P2B)      phase2: sequential fold per batch, publishes g_S[c]
//   [P1B+P2B, NBLK)     phase3: per-(chunk,batch) output scan, spins on g_S[c]
// ---------------------------------------------------------------------------
__global__ void __launch_bounds__(512)
hippo_fused(const float* __restrict__ inp,   // (L, B)
            const float* __restrict__ Bst,   // (L, N)
            float* __restrict__ out)         // (L, B, N)
{
    const int blk  = blockIdx.x;
    const int tid  = threadIdx.x;
    const int warp = tid >> 5;
    const int lane = tid & 31;
    const int i0   = 4 * lane;
    const float i0f = (float)i0;
    const float r0 = sqrtf(2.0f * i0 + 1.0f);
    const float r1 = sqrtf(2.0f * i0 + 3.0f);
    const float r2 = sqrtf(2.0f * i0 + 5.0f);
    const float r3 = sqrtf(2.0f * i0 + 7.0f);

    __shared__ float sh_s[NQ];
    __shared__ float sh_part[4][NQ];

    if (blk < P1B) {
        // ------------------- PHASE 1 -------------------
        const int chunk = blk / 10;
        const int wic   = (blk % 10) * 16 + warp;    // 0..159
        const int tbase = chunk * TQ;

        if (wic < NQ) {
            const int j = wic;                        // basis vector e_j
            float s0 = (i0     == j) ? 1.f : 0.f;
            float s1 = (i0 + 1 == j) ? 1.f : 0.f;
            float s2 = (i0 + 2 == j) ? 1.f : 0.f;
            float s3 = (i0 + 3 == j) ? 1.f : 0.f;
            #pragma unroll 4
            for (int s = 0; s < TQ; s++) {
                float tt = 2.0f * (float)(tbase + s + 1);
                hippo_step(s0, s1, s2, s3, tt, i0f, r0, r1, r2, r3,
                           0.f, 0.f, 0.f, 0.f, lane);
            }
            *reinterpret_cast<float4*>(&g_M[chunk][j][i0]) = make_float4(s0, s1, s2, s3);
        } else {
            const int b = wic - NQ;                   // particular, batch b
            float s0 = 0.f, s1 = 0.f, s2 = 0.f, s3 = 0.f;
            #pragma unroll 4
            for (int s = 0; s < TQ; s++) {
                const int t = tbase + s;
                float tt = 2.0f * (float)(t + 1);
                float4 Bv = *reinterpret_cast<const float4*>(Bst + t * NQ + i0);
                float  iv = inp[t * BQ + b];
                hippo_step(s0, s1, s2, s3, tt, i0f, r0, r1, r2, r3,
                           iv * Bv.x, iv * Bv.y, iv * Bv.z, iv * Bv.w, lane);
            }
            *reinterpret_cast<float4*>(&g_P[chunk][b][i0]) = make_float4(s0, s1, s2, s3);
        }
        __syncthreads();
        if (tid == 0) { __threadfence(); atomicAdd(&g_p1done, 1); }

    } else if (blk < P1B + P2B) {
        // ------------------- PHASE 2 -------------------
        const int b  = blk - P1B;
        const int i  = tid & 127;
        const int jw = tid >> 7;                      // 0..3

        if (tid == 0) {
            while (*(volatile int*)&g_p1done < P1B) __nanosleep(128);
            __threadfence();
        }
        if (tid < NQ) sh_s[tid] = 0.f;
        __syncthreads();

        float mcur[32], mnxt[32];
        #pragma unroll
        for (int jj = 0; jj < 32; jj++) mcur[jj] = g_M[0][jw * 32 + jj][i];

        for (int c = 0; c < CQ; c++) {
            if (tid < NQ) g_S[c][b][tid] = sh_s[tid];   // publish start state
            if (c + 1 < CQ) {
                #pragma unroll
                for (int jj = 0; jj < 32; jj++) mnxt[jj] = g_M[c + 1][jw * 32 + jj][i];
            }
            float a = 0.f;
            #pragma unroll
            for (int jj = 0; jj < 32; jj++) a = fmaf(mcur[jj], sh_s[jw * 32 + jj], a);
            sh_part[jw][i] = a;
            __syncthreads();                             // also orders g_S stores
            if (tid == 0) { __threadfence(); atomicAdd(&g_p2cnt[c], 1); }
            if (tid < NQ) {
                sh_s[tid] = g_P[c][b][tid] + sh_part[0][tid] + sh_part[1][tid]
                          + sh_part[2][tid] + sh_part[3][tid];
            }
            __syncthreads();
            #pragma unroll
            for (int jj = 0; jj < 32; jj++) mcur[jj] = mnxt[jj];
        }

    } else {
        // ------------------- PHASE 3 -------------------
        const int p     = (blk - P1B - P2B) * 16 + warp;  // 0..1023
        const int chunk = p >> 5;
        const int b     = p & 31;
        const int tbase = chunk * TQ;

        while (*(volatile int*)&g_p2cnt[chunk] < BQ) __nanosleep(128);
        __threadfence();
        __syncwarp();

        float4 sv = *reinterpret_cast<const float4*>(&g_S[chunk][b][i0]);
        float s0 = sv.x, s1 = sv.y, s2 = sv.z, s3 = sv.w;

        float4 Bv = *reinterpret_cast<const float4*>(Bst + tbase * NQ + i0);
        float  iv = inp[tbase * BQ + b];

        #pragma unroll 4
        for (int s = 0; s < TQ; s++) {
            const int t = tbase + s;
            float4 nB; float niv;
            if (s + 1 < TQ) {
                nB  = *reinterpret_cast<const float4*>(Bst + (t + 1) * NQ + i0);
                niv = inp[(t + 1) * BQ + b];
            } else { nB = Bv; niv = iv; }
            float tt = 2.0f * (float)(t + 1);
            hippo_step(s0, s1, s2, s3, tt, i0f, r0, r1, r2, r3,
                       iv * Bv.x, iv * Bv.y, iv * Bv.z, iv * Bv.w, lane);
            *reinterpret_cast<float4*>(out + (size_t)t * (BQ * NQ) + b * NQ + i0) =
                make_float4(s0, s1, s2, s3);
            Bv = nB; iv = niv;
        }
    }
}

extern "C" void kernel_launch(void* const* d_in, const int* in_sizes, int n_in,
                              void* d_out, int out_size) {
    const float* inputs = (const float*)d_in[0];   // (L, B)
    // d_in[1] = A_stacked (unused: operator reconstructed analytically)
    const float* Bst    = (const float*)d_in[2];   // (L, N)
    float* out          = (float*)d_out;           // (L, B, N)

    hippo_reset<<<1, 64>>>();
    hippo_fused<<<NBLK, 512>>>(inputs, Bst, out);
}